// round 14
// baseline (speedup 1.0000x reference)
#include <cuda_runtime.h>

#define MQ 32
#define NG 256
#define DD 128
#define QH 16
#define NPAIRJOB 496   // C(32,2) quad-pair jobs

__device__ __forceinline__ unsigned long long pack2(float lo, float hi) {
    unsigned long long r;
    asm("mov.b64 %0, {%1, %2};" : "=l"(r) : "f"(lo), "f"(hi));
    return r;
}
__device__ __forceinline__ unsigned long long fma2(unsigned long long a,
                                                   unsigned long long b,
                                                   unsigned long long c) {
    unsigned long long d;
    asm("fma.rn.f32x2 %0, %1, %2, %3;" : "=l"(d) : "l"(a), "l"(b), "l"(c));
    return d;
}
__device__ __forceinline__ void unpack2(unsigned long long v, float& lo, float& hi) {
    asm("mov.b64 {%0, %1}, %2;" : "=f"(lo), "=f"(hi) : "l"(v));
}

// Symmetry kernel. outer(u) is symmetric, so for a<b:
//   |p-M'_ab| + |p-M'_ba| = 2*max(D, |p - S|),  D=|Mp_ab-Mp_ba|/2,
//   S=(Mp_ab+Mp_ba)/2+ze  (both precomputed constants).
// Thread P<496 owns quad-pair (alpha<beta): 16 unordered pairs = 32 ordered
// elements for 27 fma-slots (was 51). Diagonal quads (320 terms/query) are
// folded into the epilogue from 2KB of precomputed shared constants.
// pen(i,j) = NE*ze + 0.5*( su^2 - smRaw - NE*ze + Sum|z'| ).
__global__ __launch_bounds__(512, 2)
void jacc_pen_kernel(const float* __restrict__ qf,
                     const float* __restrict__ x,
                     const float* __restrict__ Mp,
                     const float* __restrict__ zep,
                     float* __restrict__ out) {
    const int j     = blockIdx.x >> 1;
    const int ibase = (blockIdx.x & 1) * QH;
    const int t = threadIdx.x;
    const float ze = *zep;

    __shared__ __align__(16) float u_s[QH][DD];   // 8 KB
    __shared__ float part_s[QH][128];             // 8 KB
    __shared__ float su_s[QH], sv_s[QH];
    __shared__ float sMw_s[16];
    __shared__ __align__(16) float nMd_s[128];    // -Mp[a][a]-ze
    __shared__ float nSd_s[192];                  // -(Mp_ab+Mp_ba)/2 - ze (in-quad)
    __shared__ float Dd_s[192];                   // |Mp_ab-Mp_ba|/2      (in-quad)

    const float* __restrict__ xj = x + j * DD;

    // ---- u[i][d] = max(qf[ibase+i][d], x[j][d]) ----
    #pragma unroll
    for (int k = 0; k < (QH * DD) / 512; ++k) {
        int e = t + 512 * k;
        int i = e >> 7;
        int d = e & (DD - 1);
        u_s[i][d] = fmaxf(qf[(ibase + i) * DD + d], xj[d]);
    }

    // ---- dist0 row sums: warp w handles query w ----
    {
        int i = t >> 5;
        int l = t & 31;
        float4 q4 = *reinterpret_cast<const float4*>(qf + (ibase + i) * DD + l * 4);
        float4 x4 = *reinterpret_cast<const float4*>(xj + l * 4);
        float su = (fmaxf(q4.x, x4.x) + fmaxf(q4.y, x4.y))
                 + (fmaxf(q4.z, x4.z) + fmaxf(q4.w, x4.w));
        float sv = (fminf(q4.x, x4.x) + fminf(q4.y, x4.y))
                 + (fminf(q4.z, x4.z) + fminf(q4.w, x4.w));
        #pragma unroll
        for (int off = 16; off >= 1; off >>= 1) {
            su += __shfl_xor_sync(0xffffffffu, su, off);
            sv += __shfl_xor_sync(0xffffffffu, sv, off);
        }
        if (l == 0) { su_s[i] = su; sv_s[i] = sv; }
    }

    // ---- Job decode + per-thread pair constants ----
    const bool isMain = (t < NPAIRJOB);
    int alpha = 0, beta = 1;
    unsigned long long nS2[4][2] = {{0,0},{0,0},{0,0},{0,0}};
    float Dv[4][4] = {{0}};
    float msum = 0.0f;

    if (isMain) {
        float ff = sqrtf(8.0f * (float)t + 1.0f);
        beta = (int)((1.0f + ff) * 0.5f);
        while (beta * (beta + 1) / 2 <= t) ++beta;
        while (beta * (beta - 1) / 2 > t) --beta;
        alpha = t - beta * (beta - 1) / 2;

        float mm[4][4], tt[4][4];
        #pragma unroll
        for (int i = 0; i < 4; ++i) {
            float4 r = *reinterpret_cast<const float4*>(Mp + (4 * alpha + i) * DD + 4 * beta);
            mm[i][0] = r.x; mm[i][1] = r.y; mm[i][2] = r.z; mm[i][3] = r.w;
        }
        #pragma unroll
        for (int jj = 0; jj < 4; ++jj) {
            float4 c = *reinterpret_cast<const float4*>(Mp + (4 * beta + jj) * DD + 4 * alpha);
            tt[0][jj] = c.x; tt[1][jj] = c.y; tt[2][jj] = c.z; tt[3][jj] = c.w;
        }
        #pragma unroll
        for (int i = 0; i < 4; ++i) {
            float s0 = mm[i][0] + tt[i][0];
            float s1 = mm[i][1] + tt[i][1];
            float s2 = mm[i][2] + tt[i][2];
            float s3 = mm[i][3] + tt[i][3];
            msum += (s0 + s1) + (s2 + s3);
            nS2[i][0] = pack2(-0.5f * s0 - ze, -0.5f * s1 - ze);
            nS2[i][1] = pack2(-0.5f * s2 - ze, -0.5f * s3 - ze);
            Dv[i][0] = 0.5f * fabsf(mm[i][0] - tt[i][0]);
            Dv[i][1] = 0.5f * fabsf(mm[i][1] - tt[i][1]);
            Dv[i][2] = 0.5f * fabsf(mm[i][2] - tt[i][2]);
            Dv[i][3] = 0.5f * fabsf(mm[i][3] - tt[i][3]);
        }
    }

    // ---- Diagonal-quad constants into shared (threads < 192 / < 128) ----
    if (t < 192) {
        const int I6[6] = {0, 0, 0, 1, 1, 2};
        const int J6[6] = {1, 2, 3, 2, 3, 3};
        int q = t / 6, pp = t % 6;
        int a = 4 * q + I6[pp], b = 4 * q + J6[pp];
        float mab = Mp[a * DD + b], mba = Mp[b * DD + a];
        nSd_s[t] = -0.5f * (mab + mba) - ze;
        Dd_s[t]  = 0.5f * fabsf(mab - mba);
        msum += mab + mba;
    }
    if (t < 128) {
        float maa = Mp[t * DD + t];
        nMd_s[t] = -maa - ze;
        msum += maa;
    }

    // ---- warp-reduce msum ----
    #pragma unroll
    for (int off = 16; off >= 1; off >>= 1)
        msum += __shfl_xor_sync(0xffffffffu, msum, off);
    if ((t & 31) == 0) sMw_s[t >> 5] = msum;

    __syncthreads();

    // ---- Hot loop: scaled pair terms max(D, |ua*ub - S|), 4 queries/pass ----
    const float* ua_p = &u_s[0][4 * alpha];
    const float* ub_p = &u_s[0][4 * beta];
    float* st_p = &part_s[0][t >> 2];
    #pragma unroll 1
    for (int ig = 0; ig < QH; ig += 4) {
        float w[4];
        #pragma unroll
        for (int s = 0; s < 4; ++s) {
            float4 va = *reinterpret_cast<const float4*>(ua_p + s * DD);
            ulonglong2 cb = *reinterpret_cast<const ulonglong2*>(ub_p + s * DD);
            unsigned long long ua2[4] = {
                pack2(va.x, va.x), pack2(va.y, va.y),
                pack2(va.z, va.z), pack2(va.w, va.w)
            };

            float acc[4] = {0.0f, 0.0f, 0.0f, 0.0f};
            #pragma unroll
            for (int i = 0; i < 4; ++i) {
                float lo, hi;
                unpack2(fma2(ua2[i], cb.x, nS2[i][0]), lo, hi);
                acc[0] += fmaxf(fabsf(lo), Dv[i][0]);   // FMNMX(alu) + FADD(fma)
                acc[1] += fmaxf(fabsf(hi), Dv[i][1]);
                unpack2(fma2(ua2[i], cb.y, nS2[i][1]), lo, hi);
                acc[2] += fmaxf(fabsf(lo), Dv[i][2]);
                acc[3] += fmaxf(fabsf(hi), Dv[i][3]);
            }
            w[s] = (acc[0] + acc[1]) + (acc[2] + acc[3]);
        }

        #pragma unroll
        for (int s = 0; s < 4; ++s)
            w[s] += __shfl_down_sync(0xffffffffu, w[s], 2, 4);
        #pragma unroll
        for (int s = 0; s < 4; ++s)
            w[s] += __shfl_down_sync(0xffffffffu, w[s], 1, 4);
        if ((t & 3) == 0) {
            #pragma unroll
            for (int s = 0; s < 4; ++s)
                st_p[s * 128] = isMain ? w[s] : 0.0f;   // dummy quads write 0
        }

        ua_p += 4 * DD;
        ub_p += 4 * DD;
        st_p += 4 * 128;
    }

    __syncthreads();

    // ---- Final phase: warp w finishes query w (incl. diagonal terms) ----
    {
        const int w = t >> 5;
        const int l = t & 31;

        float sm = 0.0f;
        #pragma unroll
        for (int k = 0; k < 16; ++k) sm += sMw_s[k];

        // diagonal quad l for query w
        float4 uq = *reinterpret_cast<const float4*>(&u_s[w][4 * l]);
        float uu[4] = {uq.x, uq.y, uq.z, uq.w};
        float4 md = *reinterpret_cast<const float4*>(&nMd_s[4 * l]);
        float dself = fabsf(fmaf(uu[0], uu[0], md.x))
                    + fabsf(fmaf(uu[1], uu[1], md.y))
                    + fabsf(fmaf(uu[2], uu[2], md.z))
                    + fabsf(fmaf(uu[3], uu[3], md.w));
        const int I6[6] = {0, 0, 0, 1, 1, 2};
        const int J6[6] = {1, 2, 3, 2, 3, 3};
        float dpair = 0.0f;
        #pragma unroll
        for (int pp = 0; pp < 6; ++pp) {
            float tv = fmaf(uu[I6[pp]], uu[J6[pp]], nSd_s[6 * l + pp]);
            dpair += fmaxf(fabsf(tv), Dd_s[6 * l + pp]);
        }

        float p = (part_s[w][l]      + part_s[w][l + 32])
                + (part_s[w][l + 64] + part_s[w][l + 96]);
        float tot = 2.0f * (p + dpair) + dself;   // pair terms were half-scaled
        #pragma unroll
        for (int off = 16; off >= 1; off >>= 1)
            tot += __shfl_xor_sync(0xffffffffu, tot, off);
        if (l == 0) {
            float su = su_s[w];
            const float NE = (float)(DD * DD);  // 16384
            float pen = NE * ze + 0.5f * ((su * su - sm - NE * ze) + tot);
            out[(ibase + w) * NG + j] = sv_s[w] / su - 0.001f * pen;
        }
    }
}

extern "C" void kernel_launch(void* const* d_in, const int* in_sizes, int n_in,
                              void* d_out, int out_size) {
    const float* qf = (const float*)d_in[0];   // (32, 128)
    const float* x  = (const float*)d_in[1];   // (256, 128)
    const float* Mp = (const float*)d_in[2];   // (128, 128)
    const float* ze = (const float*)d_in[3];   // scalar
    float* out = (float*)d_out;                // (32, 256)
    (void)in_sizes; (void)n_in; (void)out_size;

    jacc_pen_kernel<<<2 * NG, 512>>>(qf, x, Mp, ze, out);
}